// round 13
// baseline (speedup 1.0000x reference)
#include <cuda_runtime.h>
#include <math.h>

#define N    4096
#define F    512
#define H1   8
#define C1   8
#define CH   64
#define NCLS 7
#define AW   128    // adjacency words per row (4096/32)
#define MAXD 128    // neighbor-list capacity per row
#define KS   8      // K-split factor for GEMM1 (k-chunk = 64)
#define GB   512    // gemm blocks in k_front
#define CSRB 512    // csr blocks in k_mid
#define FULL 0xFFFFFFFFu

// ---------------- device scratch ----------------
__device__ unsigned g_adj[N * AW];        // 2MB dedupe bitmask (zero-init; csr re-clears)
__device__ int      g_nbr[N * MAXD];
__device__ int      g_deg[N];
__device__ float    g_part[KS][N * CH];   // split-K partials (8MB)
__device__ float g_feats1[N * CH];
__device__ float g_ssrc1[N * H1];
__device__ float g_stgt1[N * H1];
__device__ float g_feats2[N * 8];         // [0..6]=feats2, [7]=ssrc2 (packed)
__device__ float g_stgt2[N];

// ---------------- packed fp32x2 helpers (sm_103a FFMA2) ----------------
__device__ __forceinline__ void ffma2(unsigned long long& d,
                                      unsigned long long a,
                                      unsigned long long b) {
    asm("fma.rn.f32x2 %0, %1, %2, %0;" : "+l"(d) : "l"(a), "l"(b));
}
__device__ __forceinline__ unsigned long long pack2(float v) {
    unsigned long long p;
    asm("mov.b64 %0, {%1, %1};" : "=l"(p) : "f"(v));
    return p;
}

// ================= kernel A: GEMM1 split-K (FFMA2)  ∪  adjacency build =================
__global__ __launch_bounds__(256) void k_front(const float* __restrict__ x,
                                               const float* __restrict__ W1,
                                               const int* __restrict__ edge,
                                               int E) {
    __shared__ float xs[64][68];   // 17.4KB padded (gemm blocks only)
    const int tid = threadIdx.x;

    // allow k_mid to launch as soon as all our blocks are running (k_mid syncs on us)
    cudaTriggerProgrammaticLaunchCompletion();

    if (blockIdx.x >= GB) {
        int t = (blockIdx.x - GB) * 256 + tid;
        if (t < N) atomicOr(&g_adj[t * AW + (t >> 5)], 1u << (t & 31));
        if (t < E) {
            int r = edge[t];
            int c = edge[E + t];
            atomicOr(&g_adj[r * AW + (c >> 5)], 1u << (c & 31));
        }
        return;
    }

    const int split = blockIdx.x & (KS - 1);
    const int row0  = (blockIdx.x >> 3) * 64;
    const int kb    = split * 64;
    const int c4    = tid & 15;
    const int r0    = (tid >> 4) * 4;
    const int c0    = c4 * 4;

#pragma unroll
    for (int t = 0; t < 4; t++) {
        int idx = tid + t * 256;
        int rr = idx >> 4, cc = idx & 15;
        *(float4*)&xs[rr][cc * 4] =
            *(const float4*)(x + (size_t)(row0 + rr) * F + kb + cc * 4);
    }
    __syncthreads();

    unsigned long long acc[4][2];
#pragma unroll
    for (int r = 0; r < 4; r++) { acc[r][0] = 0ull; acc[r][1] = 0ull; }

    const float* Wb = W1 + (size_t)kb * CH + c0;

#pragma unroll
    for (int k4 = 0; k4 < 16; k4++) {
        float4 xv0 = *(const float4*)&xs[r0 + 0][k4 * 4];
        float4 xv1 = *(const float4*)&xs[r0 + 1][k4 * 4];
        float4 xv2 = *(const float4*)&xs[r0 + 2][k4 * 4];
        float4 xv3 = *(const float4*)&xs[r0 + 3][k4 * 4];
#pragma unroll
        for (int kk = 0; kk < 4; kk++) {
            ulonglong2 wa = *(const ulonglong2*)(Wb + (size_t)(k4 * 4 + kk) * CH);
            float v0 = (kk == 0) ? xv0.x : (kk == 1) ? xv0.y : (kk == 2) ? xv0.z : xv0.w;
            float v1 = (kk == 0) ? xv1.x : (kk == 1) ? xv1.y : (kk == 2) ? xv1.z : xv1.w;
            float v2 = (kk == 0) ? xv2.x : (kk == 1) ? xv2.y : (kk == 2) ? xv2.z : xv2.w;
            float v3 = (kk == 0) ? xv3.x : (kk == 1) ? xv3.y : (kk == 2) ? xv3.z : xv3.w;
            unsigned long long p0 = pack2(v0), p1 = pack2(v1);
            unsigned long long p2 = pack2(v2), p3 = pack2(v3);
            ffma2(acc[0][0], p0, wa.x); ffma2(acc[0][1], p0, wa.y);
            ffma2(acc[1][0], p1, wa.x); ffma2(acc[1][1], p1, wa.y);
            ffma2(acc[2][0], p2, wa.x); ffma2(acc[2][1], p2, wa.y);
            ffma2(acc[3][0], p3, wa.x); ffma2(acc[3][1], p3, wa.y);
        }
    }

    float* dstf = g_part[split];
#pragma unroll
    for (int r = 0; r < 4; r++) {
        *(ulonglong2*)(dstf + (size_t)(row0 + r0 + r) * CH + c0) =
            make_ulonglong2(acc[r][0], acc[r][1]);
    }
}

// ================= kernel B: csr (bitmask -> list, clear)  ∪  split-K combine =================
__global__ __launch_bounds__(256) void k_mid(const float* __restrict__ b1,
                                             const float* __restrict__ aL,
                                             const float* __restrict__ aR) {
    const int tid = threadIdx.x;

    // everything we touch depends on k_front (g_adj or g_part)
    cudaGridDependencySynchronize();
    cudaTriggerProgrammaticLaunchCompletion();

    if (blockIdx.x < CSRB) {
        const int warp = tid >> 5;
        const int lane = tid & 31;
        const int i    = blockIdx.x * 8 + warp;

        uint4 aw = ((uint4*)(g_adj + i * AW))[lane];
        ((uint4*)(g_adj + i * AW))[lane] = make_uint4(0u, 0u, 0u, 0u);

        int tot = __popc(aw.x) + __popc(aw.y) + __popc(aw.z) + __popc(aw.w);

        int pref = tot;
#pragma unroll
        for (int o = 1; o < 32; o <<= 1) {
            int t = __shfl_up_sync(FULL, pref, o);
            if (lane >= o) pref += t;
        }
        int d = __shfl_sync(FULL, pref, 31);
        if (lane == 0) g_deg[i] = d < MAXD ? d : MAXD;

        int pos  = pref - tot;
        int base = lane * 128;
        int* row = g_nbr + i * MAXD;
#pragma unroll
        for (int comp = 0; comp < 4; comp++) {
            unsigned w = (comp == 0) ? aw.x : (comp == 1) ? aw.y : (comp == 2) ? aw.z : aw.w;
            while (w) {
                int b = __ffs(w) - 1; w &= w - 1;
                if (pos < MAXD) row[pos] = base + b;
                pos++;
            }
            base += 32;
        }
        return;
    }

    __shared__ float fs[4][CH];
    const int cb  = blockIdx.x - CSRB;
    const int idx = cb * 256 + tid;
    const int c   = tid & 63;

    float f = b1[c];
#pragma unroll
    for (int s = 0; s < KS; s++) f += g_part[s][idx];
    g_feats1[idx] = f;
    fs[tid >> 6][c] = f;
    __syncthreads();

    if (tid < 32) {
        int rr = tid >> 3, h = tid & 7;
        float ss = 0.f, st = 0.f;
#pragma unroll
        for (int cc = 0; cc < C1; cc++) {
            float fv = fs[rr][h * C1 + cc];
            ss = fmaf(fv, aL[cc * H1 + h], ss);
            st = fmaf(fv, aR[cc * H1 + h], st);
        }
        int row = cb * 4 + rr;
        g_ssrc1[row * H1 + h] = ss;
        g_stgt1[row * H1 + h] = st;
    }
}

// ================= kernel C: attn layer 1 (lane-per-neighbor) + fused GEMM2 + scores2 =================
__global__ __launch_bounds__(256) void k_attn1(const float* __restrict__ W2,
                                               const float* __restrict__ b2,
                                               const float* __restrict__ aL2,
                                               const float* __restrict__ aR2) {
    __shared__ float es[8][32][9];
    __shared__ int   js[8][32];
    __shared__ float h1s[8][CH];
    __shared__ float W2s[CH * NCLS];

    const int tid  = threadIdx.x;
    const int warp = tid >> 5;
    const int lane = tid & 31;
    const int i    = blockIdx.x * 8 + warp;

    // W2 is a pure kernel input: prefetch before the dependency sync
    for (int t = tid; t < CH * NCLS; t += 256) W2s[t] = W2[t];

    cudaGridDependencySynchronize();      // wait for k_mid (deg/nbr/feats1/scores)
    cudaTriggerProgrammaticLaunchCompletion();   // AFTER sync: attn2 may pre-read k_mid outputs
    __syncthreads();

    const int d = g_deg[i];
    const float4* stp = (const float4*)(g_stgt1 + i * H1);
    float4 sta = stp[0], stb = stp[1];
    float stv[8] = {sta.x, sta.y, sta.z, sta.w, stb.x, stb.y, stb.z, stb.w};

    const int h0 = lane >> 3;   // 0..3
    const int hB = h0 + 4;

    float ssum[8];
#pragma unroll
    for (int h = 0; h < 8; h++) ssum[h] = 0.f;
    float acc0 = 0.f, acc1 = 0.f;

    for (int base = 0; base < d; base += 32) {
        const int cnt   = min(32, d - base);
        const bool live = lane < cnt;
        int j = live ? g_nbr[i * MAXD + base + lane] : 0;
        js[warp][lane] = j;

        float e[8];
        if (live) {
            const float4* sp = (const float4*)(g_ssrc1 + j * H1);
            float4 s0 = sp[0], s1 = sp[1];
            float sv[8] = {s0.x, s0.y, s0.z, s0.w, s1.x, s1.y, s1.z, s1.w};
#pragma unroll
            for (int h = 0; h < 8; h++) {
                float v = sv[h] + stv[h];
                v = v > 0.f ? v : 0.2f * v;
                e[h] = __expf(v);
                ssum[h] += e[h];
            }
        } else {
#pragma unroll
            for (int h = 0; h < 8; h++) e[h] = 0.f;
        }
#pragma unroll
        for (int h = 0; h < 8; h++) es[warp][lane][h] = e[h];
        __syncwarp();

#pragma unroll 4
        for (int k = 0; k < cnt; k++) {
            int jj   = js[warp][k];
            float p0 = es[warp][k][h0];
            float p1 = es[warp][k][hB];
            acc0 = fmaf(p0, g_feats1[jj * CH + lane],      acc0);
            acc1 = fmaf(p1, g_feats1[jj * CH + lane + 32], acc1);
        }
        __syncwarp();
    }

#pragma unroll
    for (int o = 16; o; o >>= 1)
#pragma unroll
        for (int h = 0; h < 8; h++) ssum[h] += __shfl_xor_sync(FULL, ssum[h], o);

    float sA = (h0 & 2) ? ((h0 & 1) ? ssum[3] : ssum[2])
                        : ((h0 & 1) ? ssum[1] : ssum[0]);
    float sB = (h0 & 2) ? ((h0 & 1) ? ssum[7] : ssum[6])
                        : ((h0 & 1) ? ssum[5] : ssum[4]);
    acc0 /= sA;
    acc1 /= sB;
    acc0 = acc0 > 0.f ? acc0 : expm1f(acc0);   // ELU
    acc1 = acc1 > 0.f ? acc1 : expm1f(acc1);

    h1s[warp][lane]      = acc0;
    h1s[warp][lane + 32] = acc1;
    __syncwarp();

    // fused GEMM2 (64->7) + layer-2 score projections
    float f2 = 0.f;
    if (lane < NCLS) {
        f2 = b2[lane];
        const float* hr = h1s[warp];
#pragma unroll 8
        for (int k = 0; k < CH; k++) f2 = fmaf(hr[k], W2s[k * NCLS + lane], f2);
    }

    float pl = (lane < NCLS) ? f2 * aL2[lane] : 0.f;
    float pr = (lane < NCLS) ? f2 * aR2[lane] : 0.f;
#pragma unroll
    for (int o = 16; o; o >>= 1) {
        pl += __shfl_xor_sync(FULL, pl, o);
        pr += __shfl_xor_sync(FULL, pr, o);
    }
    // pack: feats2[i][0..6] = f2, feats2[i][7] = ssrc2 (butterfly left pl in all lanes)
    if (lane < 8) g_feats2[i * 8 + lane] = (lane < NCLS) ? f2 : pl;
    if (lane == 0) g_stgt2[i] = pr;
}

// ---------------- kernel D: attn layer 2 (packed ssrc2; PDL prefetch of indices) ----------------
__global__ __launch_bounds__(256) void k_attn2(float* __restrict__ out) {
    const int tid  = threadIdx.x;
    const int warp = tid >> 5;
    const int lane = tid & 31;
    const int i    = blockIdx.x * 8 + warp;

    // deg/nbr come from k_mid, which is complete by the time attn1 triggers us
    // (attn1 triggers AFTER its own dependency sync). Prefetch the index chain
    // while attn1 is still computing feats2.
    const int d  = g_deg[i];
    const int c0 = min(32, d);
    int j0 = (lane < c0) ? g_nbr[i * MAXD + lane] : 0;

    cudaGridDependencySynchronize();   // now feats2/stgt2 are valid

    const float stg = g_stgt2[i];

    float ssum = 0.f;
    float a0 = 0.f, a1 = 0.f, a2 = 0.f, a3 = 0.f, a4 = 0.f, a5 = 0.f, a6 = 0.f;

    for (int base = 0; base < d; base += 32) {
        const int cnt = min(32, d - base);
        if (lane < cnt) {
            int j = (base == 0) ? j0 : g_nbr[i * MAXD + base + lane];
            const float4* fp = (const float4*)(g_feats2 + j * 8);
            float4 f0 = fp[0], f1 = fp[1];
            float v = f1.w + stg;              // ssrc2 packed in element 7
            v = v > 0.f ? v : 0.2f * v;
            float p = __expf(v);
            ssum += p;
            a0 = fmaf(p, f0.x, a0); a1 = fmaf(p, f0.y, a1);
            a2 = fmaf(p, f0.z, a2); a3 = fmaf(p, f0.w, a3);
            a4 = fmaf(p, f1.x, a4); a5 = fmaf(p, f1.y, a5);
            a6 = fmaf(p, f1.z, a6);
        }
    }
#pragma unroll
    for (int o = 16; o; o >>= 1) {
        ssum += __shfl_xor_sync(FULL, ssum, o);
        a0 += __shfl_xor_sync(FULL, a0, o);
        a1 += __shfl_xor_sync(FULL, a1, o);
        a2 += __shfl_xor_sync(FULL, a2, o);
        a3 += __shfl_xor_sync(FULL, a3, o);
        a4 += __shfl_xor_sync(FULL, a4, o);
        a5 += __shfl_xor_sync(FULL, a5, o);
        a6 += __shfl_xor_sync(FULL, a6, o);
    }
    if (lane == 0) {
        float inv = 1.f / ssum;
        float* o7 = out + (size_t)i * NCLS;
        o7[0] = a0 * inv; o7[1] = a1 * inv; o7[2] = a2 * inv;
        o7[3] = a3 * inv; o7[4] = a4 * inv; o7[5] = a5 * inv;
        o7[6] = a6 * inv;
    }
}

// ---------------- launch ----------------
extern "C" void kernel_launch(void* const* d_in, const int* in_sizes, int n_in,
                              void* d_out, int out_size) {
    const float* x    = (const float*)d_in[0];
    const int*   edge = (const int*)  d_in[1];
    const float* W1   = (const float*)d_in[2];
    const float* b1   = (const float*)d_in[3];
    const float* aL1  = (const float*)d_in[4];
    const float* aR1  = (const float*)d_in[5];
    const float* W2   = (const float*)d_in[6];
    const float* b2   = (const float*)d_in[7];
    const float* aL2  = (const float*)d_in[8];
    const float* aR2  = (const float*)d_in[9];
    float* out = (float*)d_out;

    const int E   = in_sizes[1] / 2;
    const int nt  = (E > N ? E : N);
    const int adjB = (nt + 255) / 256;

    // PDL attribute for dependent launches
    cudaLaunchAttribute pdl[1];
    pdl[0].id = cudaLaunchAttributeProgrammaticStreamSerialization;
    pdl[0].val.programmaticStreamSerializationAllowed = 1;

    k_front<<<GB + adjB, 256>>>(x, W1, edge, E);

    {
        cudaLaunchConfig_t cfg = {};
        cfg.gridDim  = dim3(CSRB + (N * CH) / 256);
        cfg.blockDim = dim3(256);
        cfg.attrs = pdl; cfg.numAttrs = 1;
        cudaLaunchKernelEx(&cfg, k_mid, b1, aL1, aR1);
    }
    {
        cudaLaunchConfig_t cfg = {};
        cfg.gridDim  = dim3(N / 8);
        cfg.blockDim = dim3(256);
        cfg.attrs = pdl; cfg.numAttrs = 1;
        cudaLaunchKernelEx(&cfg, k_attn1, W2, b2, aL2, aR2);
    }
    {
        cudaLaunchConfig_t cfg = {};
        cfg.gridDim  = dim3(N / 8);
        cfg.blockDim = dim3(256);
        cfg.attrs = pdl; cfg.numAttrs = 1;
        cudaLaunchKernelEx(&cfg, k_attn2, out);
    }
}

// round 14
// speedup vs baseline: 1.0523x; 1.0523x over previous
#include <cuda_runtime.h>
#include <math.h>

#define N    4096
#define F    512
#define H1   8
#define C1   8
#define CH   64
#define NCLS 7
#define AW   128    // adjacency words per row (4096/32)
#define MAXD 128    // neighbor-list capacity per row
#define KS   8      // K-split factor for GEMM1 (k-chunk = 64)
#define GB   512    // gemm blocks in k_front
#define CSRB 512    // csr blocks in k_mid
#define ATTNB 512   // blocks in fused attn kernel (must be <= 4*148 for barrier safety)
#define FULL 0xFFFFFFFFu

// ---------------- device scratch ----------------
__device__ unsigned g_adj[N * AW];        // 2MB dedupe bitmask (zero-init; csr re-clears)
__device__ int      g_nbr[N * MAXD];
__device__ int      g_deg[N];
__device__ float    g_part[KS][N * CH];   // split-K partials (8MB)
__device__ float g_feats1[N * CH];
__device__ float g_ssrc1[N * H1];
__device__ float g_stgt1[N * H1];
__device__ float g_feats2[N * 8];         // [0..6]=feats2, [7]=ssrc2 (packed)
__device__ float g_stgt2[N];
__device__ unsigned g_bar;                // ticket barrier (monotonic, replay-safe)

// ---------------- packed fp32x2 helpers (sm_103a FFMA2) ----------------
__device__ __forceinline__ void ffma2(unsigned long long& d,
                                      unsigned long long a,
                                      unsigned long long b) {
    asm("fma.rn.f32x2 %0, %1, %2, %0;" : "+l"(d) : "l"(a), "l"(b));
}
__device__ __forceinline__ unsigned long long pack2(float v) {
    unsigned long long p;
    asm("mov.b64 %0, {%1, %1};" : "=l"(p) : "f"(v));
    return p;
}

// ================= kernel A: GEMM1 split-K (FFMA2)  ∪  adjacency build =================
__global__ __launch_bounds__(256) void k_front(const float* __restrict__ x,
                                               const float* __restrict__ W1,
                                               const int* __restrict__ edge,
                                               int E) {
    __shared__ float xs[64][68];   // 17.4KB padded (gemm blocks only)
    const int tid = threadIdx.x;

    if (blockIdx.x >= GB) {
        int t = (blockIdx.x - GB) * 256 + tid;
        if (t < N) atomicOr(&g_adj[t * AW + (t >> 5)], 1u << (t & 31));
        if (t < E) {
            int r = edge[t];
            int c = edge[E + t];
            atomicOr(&g_adj[r * AW + (c >> 5)], 1u << (c & 31));
        }
        return;
    }

    const int split = blockIdx.x & (KS - 1);
    const int row0  = (blockIdx.x >> 3) * 64;
    const int kb    = split * 64;
    const int c4    = tid & 15;
    const int r0    = (tid >> 4) * 4;
    const int c0    = c4 * 4;

#pragma unroll
    for (int t = 0; t < 4; t++) {
        int idx = tid + t * 256;
        int rr = idx >> 4, cc = idx & 15;
        *(float4*)&xs[rr][cc * 4] =
            *(const float4*)(x + (size_t)(row0 + rr) * F + kb + cc * 4);
    }
    __syncthreads();

    unsigned long long acc[4][2];
#pragma unroll
    for (int r = 0; r < 4; r++) { acc[r][0] = 0ull; acc[r][1] = 0ull; }

    const float* Wb = W1 + (size_t)kb * CH + c0;

#pragma unroll
    for (int k4 = 0; k4 < 16; k4++) {
        float4 xv0 = *(const float4*)&xs[r0 + 0][k4 * 4];
        float4 xv1 = *(const float4*)&xs[r0 + 1][k4 * 4];
        float4 xv2 = *(const float4*)&xs[r0 + 2][k4 * 4];
        float4 xv3 = *(const float4*)&xs[r0 + 3][k4 * 4];
#pragma unroll
        for (int kk = 0; kk < 4; kk++) {
            ulonglong2 wa = *(const ulonglong2*)(Wb + (size_t)(k4 * 4 + kk) * CH);
            float v0 = (kk == 0) ? xv0.x : (kk == 1) ? xv0.y : (kk == 2) ? xv0.z : xv0.w;
            float v1 = (kk == 0) ? xv1.x : (kk == 1) ? xv1.y : (kk == 2) ? xv1.z : xv1.w;
            float v2 = (kk == 0) ? xv2.x : (kk == 1) ? xv2.y : (kk == 2) ? xv2.z : xv2.w;
            float v3 = (kk == 0) ? xv3.x : (kk == 1) ? xv3.y : (kk == 2) ? xv3.z : xv3.w;
            unsigned long long p0 = pack2(v0), p1 = pack2(v1);
            unsigned long long p2 = pack2(v2), p3 = pack2(v3);
            ffma2(acc[0][0], p0, wa.x); ffma2(acc[0][1], p0, wa.y);
            ffma2(acc[1][0], p1, wa.x); ffma2(acc[1][1], p1, wa.y);
            ffma2(acc[2][0], p2, wa.x); ffma2(acc[2][1], p2, wa.y);
            ffma2(acc[3][0], p3, wa.x); ffma2(acc[3][1], p3, wa.y);
        }
    }

    float* dstf = g_part[split];
#pragma unroll
    for (int r = 0; r < 4; r++) {
        *(ulonglong2*)(dstf + (size_t)(row0 + r0 + r) * CH + c0) =
            make_ulonglong2(acc[r][0], acc[r][1]);
    }
}

// ================= kernel B: csr (bitmask -> list, clear)  ∪  split-K combine =================
__global__ __launch_bounds__(256) void k_mid(const float* __restrict__ b1,
                                             const float* __restrict__ aL,
                                             const float* __restrict__ aR) {
    const int tid = threadIdx.x;

    if (blockIdx.x < CSRB) {
        const int warp = tid >> 5;
        const int lane = tid & 31;
        const int i    = blockIdx.x * 8 + warp;

        uint4 aw = ((uint4*)(g_adj + i * AW))[lane];
        ((uint4*)(g_adj + i * AW))[lane] = make_uint4(0u, 0u, 0u, 0u);

        int tot = __popc(aw.x) + __popc(aw.y) + __popc(aw.z) + __popc(aw.w);

        int pref = tot;
#pragma unroll
        for (int o = 1; o < 32; o <<= 1) {
            int t = __shfl_up_sync(FULL, pref, o);
            if (lane >= o) pref += t;
        }
        int d = __shfl_sync(FULL, pref, 31);
        if (lane == 0) g_deg[i] = d < MAXD ? d : MAXD;

        int pos  = pref - tot;
        int base = lane * 128;
        int* row = g_nbr + i * MAXD;
#pragma unroll
        for (int comp = 0; comp < 4; comp++) {
            unsigned w = (comp == 0) ? aw.x : (comp == 1) ? aw.y : (comp == 2) ? aw.z : aw.w;
            while (w) {
                int b = __ffs(w) - 1; w &= w - 1;
                if (pos < MAXD) row[pos] = base + b;
                pos++;
            }
            base += 32;
        }
        return;
    }

    __shared__ float fs[4][CH];
    const int cb  = blockIdx.x - CSRB;
    const int idx = cb * 256 + tid;
    const int c   = tid & 63;

    float f = b1[c];
#pragma unroll
    for (int s = 0; s < KS; s++) f += g_part[s][idx];
    g_feats1[idx] = f;
    fs[tid >> 6][c] = f;
    __syncthreads();

    if (tid < 32) {
        int rr = tid >> 3, h = tid & 7;
        float ss = 0.f, st = 0.f;
#pragma unroll
        for (int cc = 0; cc < C1; cc++) {
            float fv = fs[rr][h * C1 + cc];
            ss = fmaf(fv, aL[cc * H1 + h], ss);
            st = fmaf(fv, aR[cc * H1 + h], st);
        }
        int row = cb * 4 + rr;
        g_ssrc1[row * H1 + h] = ss;
        g_stgt1[row * H1 + h] = st;
    }
}

// ================= kernel C: FUSED attention (layer1 + GEMM2 + scores2 | barrier | layer2) =================
// grid = 512, 256 threads. __launch_bounds__(256,4) guarantees >=4 blocks/SM resident
// -> all 512 blocks co-resident (592 slots) -> the ticket barrier cannot deadlock.
__global__ __launch_bounds__(256, 4) void k_attn(const float* __restrict__ W2,
                                                 const float* __restrict__ b2,
                                                 const float* __restrict__ aL2,
                                                 const float* __restrict__ aR2,
                                                 float* __restrict__ out) {
    __shared__ float es[8][32][9];
    __shared__ int   js[8][32];
    __shared__ float h1s[8][CH];
    __shared__ float W2s[CH * NCLS];

    const int tid  = threadIdx.x;
    const int warp = tid >> 5;
    const int lane = tid & 31;
    const int i    = blockIdx.x * 8 + warp;

    for (int t = tid; t < CH * NCLS; t += 256) W2s[t] = W2[t];
    __syncthreads();

    const int d = g_deg[i];
    const float4* stp = (const float4*)(g_stgt1 + i * H1);
    float4 sta = stp[0], stb = stp[1];
    float stv[8] = {sta.x, sta.y, sta.z, sta.w, stb.x, stb.y, stb.z, stb.w};

    const int h0 = lane >> 3;   // 0..3
    const int hB = h0 + 4;

    float ssum[8];
#pragma unroll
    for (int h = 0; h < 8; h++) ssum[h] = 0.f;
    float acc0 = 0.f, acc1 = 0.f;

    for (int base = 0; base < d; base += 32) {
        const int cnt   = min(32, d - base);
        const bool live = lane < cnt;
        int j = live ? g_nbr[i * MAXD + base + lane] : 0;
        js[warp][lane] = j;

        float e[8];
        if (live) {
            const float4* sp = (const float4*)(g_ssrc1 + j * H1);
            float4 s0 = sp[0], s1 = sp[1];
            float sv[8] = {s0.x, s0.y, s0.z, s0.w, s1.x, s1.y, s1.z, s1.w};
#pragma unroll
            for (int h = 0; h < 8; h++) {
                float v = sv[h] + stv[h];
                v = v > 0.f ? v : 0.2f * v;
                e[h] = __expf(v);
                ssum[h] += e[h];
            }
        } else {
#pragma unroll
            for (int h = 0; h < 8; h++) e[h] = 0.f;
        }
#pragma unroll
        for (int h = 0; h < 8; h++) es[warp][lane][h] = e[h];
        __syncwarp();

#pragma unroll 4
        for (int k = 0; k < cnt; k++) {
            int jj   = js[warp][k];
            float p0 = es[warp][k][h0];
            float p1 = es[warp][k][hB];
            acc0 = fmaf(p0, g_feats1[jj * CH + lane],      acc0);
            acc1 = fmaf(p1, g_feats1[jj * CH + lane + 32], acc1);
        }
        __syncwarp();
    }

#pragma unroll
    for (int o = 16; o; o >>= 1)
#pragma unroll
        for (int h = 0; h < 8; h++) ssum[h] += __shfl_xor_sync(FULL, ssum[h], o);

    float sA = (h0 & 2) ? ((h0 & 1) ? ssum[3] : ssum[2])
                        : ((h0 & 1) ? ssum[1] : ssum[0]);
    float sB = (h0 & 2) ? ((h0 & 1) ? ssum[7] : ssum[6])
                        : ((h0 & 1) ? ssum[5] : ssum[4]);
    acc0 /= sA;
    acc1 /= sB;
    acc0 = acc0 > 0.f ? acc0 : expm1f(acc0);   // ELU
    acc1 = acc1 > 0.f ? acc1 : expm1f(acc1);

    h1s[warp][lane]      = acc0;
    h1s[warp][lane + 32] = acc1;
    __syncwarp();

    // fused GEMM2 (64->7) + layer-2 score projections
    float f2 = 0.f;
    if (lane < NCLS) {
        f2 = b2[lane];
        const float* hr = h1s[warp];
#pragma unroll 8
        for (int k = 0; k < CH; k++) f2 = fmaf(hr[k], W2s[k * NCLS + lane], f2);
    }

    float pl = (lane < NCLS) ? f2 * aL2[lane] : 0.f;
    float pr = (lane < NCLS) ? f2 * aR2[lane] : 0.f;
#pragma unroll
    for (int o = 16; o; o >>= 1) {
        pl += __shfl_xor_sync(FULL, pl, o);
        pr += __shfl_xor_sync(FULL, pr, o);
    }
    // pack: feats2[i][0..6] = f2, feats2[i][7] = ssrc2 (butterfly left pl in all lanes)
    if (lane < 8) g_feats2[i * 8 + lane] = (lane < NCLS) ? f2 : pl;
    if (lane == 0) g_stgt2[i] = pr;

    // ---------- device-wide ticket barrier (monotonic -> replay-safe, no reset) ----------
    __threadfence();          // publish feats2/stgt2 to L2 before arriving
    __syncthreads();
    __shared__ unsigned s_tgt;
    if (tid == 0) {
        unsigned ticket = atomicAdd(&g_bar, 1u);
        s_tgt = (ticket / ATTNB) * ATTNB + ATTNB;   // target for THIS launch's epoch
    }
    __syncthreads();
    // prefetch phase-2 indices while spinning is handled below (deg/nbr are phase-1 inputs)
    const int c0p = min(32, d);
    int j0 = (lane < c0p) ? g_nbr[i * MAXD + lane] : 0;
    if (tid == 0) {
        volatile unsigned* bp = &g_bar;
        while (*bp < s_tgt) __nanosleep(64);
    }
    __syncthreads();
    __threadfence();          // acquire: order phase-2 loads after barrier

    // ---------- phase 2: attention layer 2 (packed ssrc2 in feats2[7]) ----------
    const float stg = g_stgt2[i];

    float zsum = 0.f;
    float a0 = 0.f, a1 = 0.f, a2 = 0.f, a3 = 0.f, a4 = 0.f, a5 = 0.f, a6 = 0.f;

    for (int base = 0; base < d; base += 32) {
        const int cnt = min(32, d - base);
        if (lane < cnt) {
            int j = (base == 0) ? j0 : g_nbr[i * MAXD + base + lane];
            const float4* fp = (const float4*)(g_feats2 + j * 8);
            float4 f0 = fp[0], f1 = fp[1];
            float v = f1.w + stg;              // ssrc2 packed in element 7
            v = v > 0.f ? v : 0.2f * v;
            float p = __expf(v);
            zsum += p;
            a0 = fmaf(p, f0.x, a0); a1 = fmaf(p, f0.y, a1);
            a2 = fmaf(p, f0.z, a2); a3 = fmaf(p, f0.w, a3);
            a4 = fmaf(p, f1.x, a4); a5 = fmaf(p, f1.y, a5);
            a6 = fmaf(p, f1.z, a6);
        }
    }
#pragma unroll
    for (int o = 16; o; o >>= 1) {
        zsum += __shfl_xor_sync(FULL, zsum, o);
        a0 += __shfl_xor_sync(FULL, a0, o);
        a1 += __shfl_xor_sync(FULL, a1, o);
        a2 += __shfl_xor_sync(FULL, a2, o);
        a3 += __shfl_xor_sync(FULL, a3, o);
        a4 += __shfl_xor_sync(FULL, a4, o);
        a5 += __shfl_xor_sync(FULL, a5, o);
        a6 += __shfl_xor_sync(FULL, a6, o);
    }
    if (lane == 0) {
        float inv = 1.f / zsum;
        float* o7 = out + (size_t)i * NCLS;
        o7[0] = a0 * inv; o7[1] = a1 * inv; o7[2] = a2 * inv;
        o7[3] = a3 * inv; o7[4] = a4 * inv; o7[5] = a5 * inv;
        o7[6] = a6 * inv;
    }
}

// ---------------- launch ----------------
extern "C" void kernel_launch(void* const* d_in, const int* in_sizes, int n_in,
                              void* d_out, int out_size) {
    const float* x    = (const float*)d_in[0];
    const int*   edge = (const int*)  d_in[1];
    const float* W1   = (const float*)d_in[2];
    const float* b1   = (const float*)d_in[3];
    const float* aL1  = (const float*)d_in[4];
    const float* aR1  = (const float*)d_in[5];
    const float* W2   = (const float*)d_in[6];
    const float* b2   = (const float*)d_in[7];
    const float* aL2  = (const float*)d_in[8];
    const float* aR2  = (const float*)d_in[9];
    float* out = (float*)d_out;

    const int E   = in_sizes[1] / 2;
    const int nt  = (E > N ? E : N);
    const int adjB = (nt + 255) / 256;

    k_front<<<GB + adjB, 256>>>(x, W1, edge, E);
    k_mid<<<CSRB + (N * CH) / 256, 256>>>(b1, aL1, aR1);
    k_attn<<<ATTNB, 256>>>(W2, b2, aL2, aR2, out);
}

// round 15
// speedup vs baseline: 1.1275x; 1.0714x over previous
#include <cuda_runtime.h>
#include <math.h>

#define N    4096
#define F    512
#define H1   8
#define C1   8
#define CH   64
#define NCLS 7
#define AW   128    // adjacency words per row (4096/32)
#define MAXD 128    // neighbor-list capacity per row
#define KS   8      // K-split factor for GEMM1 (k-chunk = 64)
#define GB   512    // gemm blocks in k_front
#define CSRB 512    // csr blocks in k_mid
#define FULL 0xFFFFFFFFu

// ---------------- device scratch ----------------
__device__ unsigned g_adj[N * AW];        // 2MB dedupe bitmask (zero-init; csr re-clears)
__device__ int      g_nbr[N * MAXD];
__device__ int      g_deg[N];
__device__ float    g_part[KS][N * CH];   // split-K partials (8MB)
__device__ float g_feats1[N * CH];
__device__ float g_ssrc1[N * H1];
__device__ float g_stgt1[N * H1];
__device__ float g_feats2[N * 8];         // [0..6]=feats2, [7]=ssrc2 (packed)
__device__ float g_stgt2[N];

// ---------------- packed fp32x2 helpers (sm_103a FFMA2) ----------------
__device__ __forceinline__ void ffma2(unsigned long long& d,
                                      unsigned long long a,
                                      unsigned long long b) {
    asm("fma.rn.f32x2 %0, %1, %2, %0;" : "+l"(d) : "l"(a), "l"(b));
}
__device__ __forceinline__ unsigned long long pack2(float v) {
    unsigned long long p;
    asm("mov.b64 %0, {%1, %1};" : "=l"(p) : "f"(v));
    return p;
}

// ================= kernel A: GEMM1 split-K (FFMA2, W in smem)  ∪  adjacency build =================
__global__ __launch_bounds__(256) void k_front(const float* __restrict__ x,
                                               const float* __restrict__ W1,
                                               const int* __restrict__ edge,
                                               int E) {
    __shared__ float xs[64][68];   // 17.4KB padded
    __shared__ float ws[64][64];   // 16KB W1 k-chunk (row k, col c)
    const int tid = threadIdx.x;

    if (blockIdx.x >= GB) {
        int t = (blockIdx.x - GB) * 256 + tid;
        if (t < N) atomicOr(&g_adj[t * AW + (t >> 5)], 1u << (t & 31));
        if (t < E) {
            int r = edge[t];
            int c = edge[E + t];
            atomicOr(&g_adj[r * AW + (c >> 5)], 1u << (c & 31));
        }
        return;
    }

    const int split = blockIdx.x & (KS - 1);
    const int row0  = (blockIdx.x >> 3) * 64;
    const int kb    = split * 64;
    const int c4    = tid & 15;
    const int r0    = (tid >> 4) * 4;
    const int c0    = c4 * 4;

    // stage x tile [64 rows][64 k] and W chunk [64 k][64 cols]
#pragma unroll
    for (int t = 0; t < 4; t++) {
        int idx = tid + t * 256;
        int rr = idx >> 4, cc = idx & 15;
        *(float4*)&xs[rr][cc * 4] =
            *(const float4*)(x + (size_t)(row0 + rr) * F + kb + cc * 4);
        *(float4*)&ws[rr][cc * 4] =
            *(const float4*)(W1 + (size_t)(kb + rr) * CH + cc * 4);
    }
    __syncthreads();

    unsigned long long acc[4][2];
#pragma unroll
    for (int r = 0; r < 4; r++) { acc[r][0] = 0ull; acc[r][1] = 0ull; }

#pragma unroll
    for (int k4 = 0; k4 < 16; k4++) {
        float4 xv0 = *(const float4*)&xs[r0 + 0][k4 * 4];
        float4 xv1 = *(const float4*)&xs[r0 + 1][k4 * 4];
        float4 xv2 = *(const float4*)&xs[r0 + 2][k4 * 4];
        float4 xv3 = *(const float4*)&xs[r0 + 3][k4 * 4];
#pragma unroll
        for (int kk = 0; kk < 4; kk++) {
            ulonglong2 wa = *(const ulonglong2*)&ws[k4 * 4 + kk][c0];
            float v0 = (kk == 0) ? xv0.x : (kk == 1) ? xv0.y : (kk == 2) ? xv0.z : xv0.w;
            float v1 = (kk == 0) ? xv1.x : (kk == 1) ? xv1.y : (kk == 2) ? xv1.z : xv1.w;
            float v2 = (kk == 0) ? xv2.x : (kk == 1) ? xv2.y : (kk == 2) ? xv2.z : xv2.w;
            float v3 = (kk == 0) ? xv3.x : (kk == 1) ? xv3.y : (kk == 2) ? xv3.z : xv3.w;
            unsigned long long p0 = pack2(v0), p1 = pack2(v1);
            unsigned long long p2 = pack2(v2), p3 = pack2(v3);
            ffma2(acc[0][0], p0, wa.x); ffma2(acc[0][1], p0, wa.y);
            ffma2(acc[1][0], p1, wa.x); ffma2(acc[1][1], p1, wa.y);
            ffma2(acc[2][0], p2, wa.x); ffma2(acc[2][1], p2, wa.y);
            ffma2(acc[3][0], p3, wa.x); ffma2(acc[3][1], p3, wa.y);
        }
    }

    float* dstf = g_part[split];
#pragma unroll
    for (int r = 0; r < 4; r++) {
        *(ulonglong2*)(dstf + (size_t)(row0 + r0 + r) * CH + c0) =
            make_ulonglong2(acc[r][0], acc[r][1]);
    }
}

// ================= kernel B: csr (bitmask -> list, clear)  ∪  split-K combine =================
__global__ __launch_bounds__(256) void k_mid(const float* __restrict__ b1,
                                             const float* __restrict__ aL,
                                             const float* __restrict__ aR) {
    const int tid = threadIdx.x;

    if (blockIdx.x < CSRB) {
        const int warp = tid >> 5;
        const int lane = tid & 31;
        const int i    = blockIdx.x * 8 + warp;

        uint4 aw = ((uint4*)(g_adj + i * AW))[lane];
        ((uint4*)(g_adj + i * AW))[lane] = make_uint4(0u, 0u, 0u, 0u);

        int tot = __popc(aw.x) + __popc(aw.y) + __popc(aw.z) + __popc(aw.w);

        int pref = tot;
#pragma unroll
        for (int o = 1; o < 32; o <<= 1) {
            int t = __shfl_up_sync(FULL, pref, o);
            if (lane >= o) pref += t;
        }
        int d = __shfl_sync(FULL, pref, 31);
        if (lane == 0) g_deg[i] = d < MAXD ? d : MAXD;

        int pos  = pref - tot;
        int base = lane * 128;
        int* row = g_nbr + i * MAXD;
#pragma unroll
        for (int comp = 0; comp < 4; comp++) {
            unsigned w = (comp == 0) ? aw.x : (comp == 1) ? aw.y : (comp == 2) ? aw.z : aw.w;
            while (w) {
                int b = __ffs(w) - 1; w &= w - 1;
                if (pos < MAXD) row[pos] = base + b;
                pos++;
            }
            base += 32;
        }
        return;
    }

    __shared__ float fs[4][CH];
    const int cb  = blockIdx.x - CSRB;
    const int idx = cb * 256 + tid;
    const int c   = tid & 63;

    float f = b1[c];
#pragma unroll
    for (int s = 0; s < KS; s++) f += g_part[s][idx];
    g_feats1[idx] = f;
    fs[tid >> 6][c] = f;
    __syncthreads();

    if (tid < 32) {
        int rr = tid >> 3, h = tid & 7;
        float ss = 0.f, st = 0.f;
#pragma unroll
        for (int cc = 0; cc < C1; cc++) {
            float fv = fs[rr][h * C1 + cc];
            ss = fmaf(fv, aL[cc * H1 + h], ss);
            st = fmaf(fv, aR[cc * H1 + h], st);
        }
        int row = cb * 4 + rr;
        g_ssrc1[row * H1 + h] = ss;
        g_stgt1[row * H1 + h] = st;
    }
}

// ================= kernel C: attn layer 1 (lane-per-neighbor) + fused GEMM2 + scores2 =================
__global__ __launch_bounds__(256) void k_attn1(const float* __restrict__ W2,
                                               const float* __restrict__ b2,
                                               const float* __restrict__ aL2,
                                               const float* __restrict__ aR2) {
    __shared__ float es[8][32][9];
    __shared__ int   js[8][32];
    __shared__ float h1s[8][CH];
    __shared__ float W2s[CH * NCLS];

    const int tid  = threadIdx.x;
    const int warp = tid >> 5;
    const int lane = tid & 31;
    const int i    = blockIdx.x * 8 + warp;

    for (int t = tid; t < CH * NCLS; t += 256) W2s[t] = W2[t];
    __syncthreads();

    const int d = g_deg[i];
    const float4* stp = (const float4*)(g_stgt1 + i * H1);
    float4 sta = stp[0], stb = stp[1];
    float stv[8] = {sta.x, sta.y, sta.z, sta.w, stb.x, stb.y, stb.z, stb.w};

    const int h0 = lane >> 3;   // 0..3
    const int hB = h0 + 4;

    float ssum[8];
#pragma unroll
    for (int h = 0; h < 8; h++) ssum[h] = 0.f;
    float acc0 = 0.f, acc1 = 0.f;

    for (int base = 0; base < d; base += 32) {
        const int cnt   = min(32, d - base);
        const bool live = lane < cnt;
        int j = live ? g_nbr[i * MAXD + base + lane] : 0;
        js[warp][lane] = j;

        float e[8];
        if (live) {
            const float4* sp = (const float4*)(g_ssrc1 + j * H1);
            float4 s0 = sp[0], s1 = sp[1];
            float sv[8] = {s0.x, s0.y, s0.z, s0.w, s1.x, s1.y, s1.z, s1.w};
#pragma unroll
            for (int h = 0; h < 8; h++) {
                float v = sv[h] + stv[h];
                v = v > 0.f ? v : 0.2f * v;
                e[h] = __expf(v);
                ssum[h] += e[h];
            }
        } else {
#pragma unroll
            for (int h = 0; h < 8; h++) e[h] = 0.f;
        }
#pragma unroll
        for (int h = 0; h < 8; h++) es[warp][lane][h] = e[h];
        __syncwarp();

#pragma unroll 4
        for (int k = 0; k < cnt; k++) {
            int jj   = js[warp][k];
            float p0 = es[warp][k][h0];
            float p1 = es[warp][k][hB];
            acc0 = fmaf(p0, g_feats1[jj * CH + lane],      acc0);
            acc1 = fmaf(p1, g_feats1[jj * CH + lane + 32], acc1);
        }
        __syncwarp();
    }

#pragma unroll
    for (int o = 16; o; o >>= 1)
#pragma unroll
        for (int h = 0; h < 8; h++) ssum[h] += __shfl_xor_sync(FULL, ssum[h], o);

    float sA = (h0 & 2) ? ((h0 & 1) ? ssum[3] : ssum[2])
                        : ((h0 & 1) ? ssum[1] : ssum[0]);
    float sB = (h0 & 2) ? ((h0 & 1) ? ssum[7] : ssum[6])
                        : ((h0 & 1) ? ssum[5] : ssum[4]);
    acc0 /= sA;
    acc1 /= sB;
    acc0 = acc0 > 0.f ? acc0 : expm1f(acc0);   // ELU
    acc1 = acc1 > 0.f ? acc1 : expm1f(acc1);

    h1s[warp][lane]      = acc0;
    h1s[warp][lane + 32] = acc1;
    __syncwarp();

    // fused GEMM2 (64->7) + layer-2 score projections
    float f2 = 0.f;
    if (lane < NCLS) {
        f2 = b2[lane];
        const float* hr = h1s[warp];
#pragma unroll 8
        for (int k = 0; k < CH; k++) f2 = fmaf(hr[k], W2s[k * NCLS + lane], f2);
    }

    float pl = (lane < NCLS) ? f2 * aL2[lane] : 0.f;
    float pr = (lane < NCLS) ? f2 * aR2[lane] : 0.f;
#pragma unroll
    for (int o = 16; o; o >>= 1) {
        pl += __shfl_xor_sync(FULL, pl, o);
        pr += __shfl_xor_sync(FULL, pr, o);
    }
    // pack: feats2[i][0..6] = f2, feats2[i][7] = ssrc2 (butterfly left pl in all lanes)
    if (lane < 8) g_feats2[i * 8 + lane] = (lane < NCLS) ? f2 : pl;
    if (lane == 0) g_stgt2[i] = pr;
}

// ---------------- kernel D: attn layer 2 (packed ssrc2 in feats2[7]) ----------------
__global__ __launch_bounds__(256) void k_attn2(float* __restrict__ out) {
    const int tid  = threadIdx.x;
    const int warp = tid >> 5;
    const int lane = tid & 31;
    const int i    = blockIdx.x * 8 + warp;

    const int d     = g_deg[i];
    const float stg = g_stgt2[i];

    float ssum = 0.f;
    float a0 = 0.f, a1 = 0.f, a2 = 0.f, a3 = 0.f, a4 = 0.f, a5 = 0.f, a6 = 0.f;

    for (int base = 0; base < d; base += 32) {
        const int cnt = min(32, d - base);
        if (lane < cnt) {
            int j = g_nbr[i * MAXD + base + lane];
            const float4* fp = (const float4*)(g_feats2 + j * 8);
            float4 f0 = fp[0], f1 = fp[1];
            float v = f1.w + stg;              // ssrc2 packed in element 7
            v = v > 0.f ? v : 0.2f * v;
            float p = __expf(v);
            ssum += p;
            a0 = fmaf(p, f0.x, a0); a1 = fmaf(p, f0.y, a1);
            a2 = fmaf(p, f0.z, a2); a3 = fmaf(p, f0.w, a3);
            a4 = fmaf(p, f1.x, a4); a5 = fmaf(p, f1.y, a5);
            a6 = fmaf(p, f1.z, a6);
        }
    }
#pragma unroll
    for (int o = 16; o; o >>= 1) {
        ssum += __shfl_xor_sync(FULL, ssum, o);
        a0 += __shfl_xor_sync(FULL, a0, o);
        a1 += __shfl_xor_sync(FULL, a1, o);
        a2 += __shfl_xor_sync(FULL, a2, o);
        a3 += __shfl_xor_sync(FULL, a3, o);
        a4 += __shfl_xor_sync(FULL, a4, o);
        a5 += __shfl_xor_sync(FULL, a5, o);
        a6 += __shfl_xor_sync(FULL, a6, o);
    }
    if (lane == 0) {
        float inv = 1.f / ssum;
        float* o7 = out + (size_t)i * NCLS;
        o7[0] = a0 * inv; o7[1] = a1 * inv; o7[2] = a2 * inv;
        o7[3] = a3 * inv; o7[4] = a4 * inv; o7[5] = a5 * inv;
        o7[6] = a6 * inv;
    }
}

// ---------------- launch ----------------
extern "C" void kernel_launch(void* const* d_in, const int* in_sizes, int n_in,
                              void* d_out, int out_size) {
    const float* x    = (const float*)d_in[0];
    const int*   edge = (const int*)  d_in[1];
    const float* W1   = (const float*)d_in[2];
    const float* b1   = (const float*)d_in[3];
    const float* aL1  = (const float*)d_in[4];
    const float* aR1  = (const float*)d_in[5];
    const float* W2   = (const float*)d_in[6];
    const float* b2   = (const float*)d_in[7];
    const float* aL2  = (const float*)d_in[8];
    const float* aR2  = (const float*)d_in[9];
    float* out = (float*)d_out;

    const int E   = in_sizes[1] / 2;
    const int nt  = (E > N ? E : N);
    const int adjB = (nt + 255) / 256;

    k_front<<<GB + adjB, 256>>>(x, W1, edge, E);
    k_mid<<<CSRB + (N * CH) / 256, 256>>>(b1, aL1, aR1);
    k_attn1<<<N / 8, 256>>>(W2, b2, aL2, aR2);
    k_attn2<<<N / 8, 256>>>(out);
}